// round 17
// baseline (speedup 1.0000x reference)
#include <cuda_runtime.h>
#include <cstdint>
#include <math.h>

#define H 128
#define MAXB 8192

__device__ float g_z[MAXB];   // pre-sigmoid logits, overwritten every call

#define CP_ASYNC_CG(dst_u32, src_ptr) \
    asm volatile("cp.async.cg.shared.global [%0], [%1], 16;" :: "r"(dst_u32), "l"(src_ptr))
#define CP_COMMIT() asm volatile("cp.async.commit_group;")
#define CP_WAIT1()  asm volatile("cp.async.wait_group 1;" ::: "memory")

// ---------------------------------------------------------------------------
// Warp-parallel 32-ary lower_bound over sorted a[0..T) (R16-proven).
// ---------------------------------------------------------------------------
__device__ __forceinline__ int lower_bound32(
    const int* __restrict__ a, int T, int key)
{
    const int lane = threadIdx.x & 31;
    int lo = 0, hi = T;
    while (hi - lo > 32) {
        const int span = hi - lo;
        const int p = lo + (span * (lane + 1)) / 33;
        const bool lt = (__ldg(&a[p]) < key);
        const unsigned m = __ballot_sync(0xffffffffu, lt);
        const int k = __popc(m);
        const int nhi = (k == 32) ? hi : lo + (span * (k + 1)) / 33;
        lo = (k == 0) ? lo : lo + (span * k) / 33 + 1;
        hi = nhi;
    }
    const int p = lo + lane;
    const bool lt = (p < hi) ? (__ldg(&a[p]) < key) : false;
    return lo + __popc(__ballot_sync(0xffffffffu, lt));
}

// ---------------------------------------------------------------------------
// Fused kernel: p-ary bounds + cp.async gather/mean (R16-proven) + per-block
// 128x128 matvec + tanh + dot(W_out) -> z. Block owns its segment end-to-end:
// no fences, no atomics, no inter-block traffic. cp.async.cg bypasses L1, so
// W_hid (64KB) stays L1-resident for the epilogue matvec.
// ---------------------------------------------------------------------------
__global__ __launch_bounds__(128, 12) void fused_kernel(
    const int*   __restrict__ token_ids,
    const int*   __restrict__ seg_ids,
    const float* __restrict__ embed,
    const float* __restrict__ W_hid,   // [H,H] row-major
    const float* __restrict__ b_hid,
    const float* __restrict__ W_out,
    const float* __restrict__ b_out,
    int T)
{
    const int seg = blockIdx.x;
    const int tid = threadIdx.x;
    const int w   = tid >> 5;
    const int l   = tid & 31;

    __shared__ __align__(16) float4 s_buf[4][2][4][32];  // 16KB gather pipeline
    __shared__ float s_part[4][H];                        // warp partials / matvec partials
    __shared__ float s_vec[H];                            // sentence mean
    __shared__ float s_red[4];
    __shared__ int   s_bounds[2];

    if (w == 0) {
        const int v = lower_bound32(seg_ids, T, seg);
        if (l == 0) s_bounds[0] = v;
    } else if (w == 1) {
        const int v = lower_bound32(seg_ids, T, seg + 1);
        if (l == 0) s_bounds[1] = v;
    }
    __syncthreads();

    const int start = s_bounds[0];
    const int end   = s_bounds[1];
    const int n     = end - start;
    const int chunks = (n + 15) >> 4;

    const unsigned int sbase =
        (unsigned int)__cvta_generic_to_shared(&s_buf[w][0][0][l]);
    const char* E = (const char*)embed;

    float4 a0 = make_float4(0.f, 0.f, 0.f, 0.f), a1 = a0;

#define FILL(c)                                                            \
    do {                                                                   \
        const int _c = (c);                                                \
        if (_c < chunks) {                                                 \
            const int _base = start + _c * 16 + w * 4;                     \
            _Pragma("unroll")                                              \
            for (int _j = 0; _j < 4; _j++) {                               \
                const int _idx = _base + _j;                               \
                if (_idx < end) {                                          \
                    const int _tok = __ldg(&token_ids[_idx]);              \
                    CP_ASYNC_CG(sbase + (unsigned int)((_c & 1) * 2048 + _j * 512), \
                                E + (size_t)_tok * 512 + l * 16);          \
                }                                                          \
            }                                                              \
        }                                                                  \
        CP_COMMIT();                                                       \
    } while (0)

    FILL(0);
    FILL(1);

    for (int c = 0; c < chunks; c++) {
        CP_WAIT1();
        const int base = c * 16 + w * 4;
        const int m    = n - base;
        const int slot = c & 1;
        if (m >= 1) { const float4 v = s_buf[w][slot][0][l];
                      a0.x += v.x; a0.y += v.y; a0.z += v.z; a0.w += v.w; }
        if (m >= 2) { const float4 v = s_buf[w][slot][1][l];
                      a1.x += v.x; a1.y += v.y; a1.z += v.z; a1.w += v.w; }
        if (m >= 3) { const float4 v = s_buf[w][slot][2][l];
                      a0.x += v.x; a0.y += v.y; a0.z += v.z; a0.w += v.w; }
        if (m >= 4) { const float4 v = s_buf[w][slot][3][l];
                      a1.x += v.x; a1.y += v.y; a1.z += v.z; a1.w += v.w; }
        FILL(c + 2);
    }
#undef FILL

    float4 asum;
    asum.x = a0.x + a1.x;  asum.y = a0.y + a1.y;
    asum.z = a0.z + a1.z;  asum.w = a0.w + a1.w;
    *(float4*)&s_part[w][4 * l] = asum;
    __syncthreads();

    const float inv = 1.0f / (float)max(n, 1);
    s_vec[tid] = ((s_part[0][tid] + s_part[1][tid]) +
                  (s_part[2][tid] + s_part[3][tid])) * inv;
    __syncthreads();   // s_vec ready; s_part free for reuse

    // ---- matvec: warp w covers k in [32w, 32w+32); lane l owns cols 4l..4l+3
    const float4* W4 = (const float4*)W_hid;   // W4[k*32 + c] = W[k][4c..4c+3]
    float4 acc = make_float4(0.f, 0.f, 0.f, 0.f);
#pragma unroll 8
    for (int kk = 0; kk < 32; kk++) {
        const int k = w * 32 + kk;
        const float  s  = s_vec[k];             // broadcast LDS
        const float4 wv = __ldg(&W4[k * 32 + l]);   // L1-resident
        acc.x += s * wv.x;  acc.y += s * wv.y;
        acc.z += s * wv.z;  acc.w += s * wv.w;
    }
    *(float4*)&s_part[w][4 * l] = acc;
    __syncthreads();

    // ---- col tid: combine, tanh, weight; reduce to scalar z ----
    const float h = (s_part[0][tid] + s_part[1][tid]) +
                    (s_part[2][tid] + s_part[3][tid]) + b_hid[tid];
    float v = tanhf(h) * W_out[tid];
#pragma unroll
    for (int off = 16; off > 0; off >>= 1)
        v += __shfl_xor_sync(0xffffffffu, v, off);
    if (l == 0) s_red[w] = v;
    __syncthreads();

    if (tid == 0)
        g_z[seg] = (s_red[0] + s_red[1]) + (s_red[2] + s_red[3]) + __ldg(b_out);
}

// ---------------------------------------------------------------------------
// BCE kernel: ONE block, 1024 threads; reads g_z + y_true, sums the clamped
// BCE, thread 0 writes the final scalar. No zeroing, no atomics, no races.
// ---------------------------------------------------------------------------
__global__ __launch_bounds__(1024) void bce_kernel(
    const float* __restrict__ y_true,
    float*       __restrict__ out,
    int B)
{
    const int t = threadIdx.x;
    __shared__ float s_red[32];

    float local = 0.f;
    for (int row = t; row < B; row += 1024) {
        const float z = g_z[row];
        const float y = __ldg(&y_true[row]);
        // log(sigmoid(z)) = -log1p(exp(-z)); log(1-sigmoid(z)) = -log1p(exp(z))
        const float lp  = fmaxf(-log1pf(expf(-z)), -100.0f);
        const float l1m = fmaxf(-log1pf(expf(z)),  -100.0f);
        local += -(y * lp + (1.0f - y) * l1m);
    }
#pragma unroll
    for (int off = 16; off > 0; off >>= 1)
        local += __shfl_xor_sync(0xffffffffu, local, off);
    if ((t & 31) == 0) s_red[t >> 5] = local;
    __syncthreads();

    if (t < 32) {
        float v = s_red[t];
#pragma unroll
        for (int off = 16; off > 0; off >>= 1)
            v += __shfl_xor_sync(0xffffffffu, v, off);
        if (t == 0) *out = v;
    }
}

// ---------------------------------------------------------------------------
extern "C" void kernel_launch(void* const* d_in, const int* in_sizes, int n_in,
                              void* d_out, int out_size)
{
    const int*   token_ids = (const int*)d_in[0];
    const int*   seg_ids   = (const int*)d_in[1];
    const float* y_true    = (const float*)d_in[2];
    const float* embed     = (const float*)d_in[3];
    const float* W_hid     = (const float*)d_in[4];
    const float* b_hid     = (const float*)d_in[5];
    const float* W_out     = (const float*)d_in[6];
    const float* b_out     = (const float*)d_in[7];

    const int T = in_sizes[0];
    const int B = in_sizes[2];
    float* out = (float*)d_out;

    fused_kernel<<<B, 128>>>(token_ids, seg_ids, embed,
                             W_hid, b_hid, W_out, b_out, T);

    bce_kernel<<<1, 1024>>>(y_true, out, B);
}